// round 1
// baseline (speedup 1.0000x reference)
#include <cuda_runtime.h>
#include <math.h>

// YOLOv4 stride-8 head: [B, A*attrs, G, G] -> [B, G*G*A, attrs] with
// sigmoid/exp transforms, grid offsets and anchor scaling fused in.
//
// Shapes for this problem: B=16, A=3, attrs=85, G=76.

#define N_ANCH 3
#define N_ATTRS 85
#define SCALE_XY 1.2f

__global__ __launch_bounds__(256)
void yolo_kernel(const float* __restrict__ x,
                 const int*   __restrict__ dim_raw,   // input_dim (int or float bits)
                 float*       __restrict__ out,
                 int G, int GG, int total /* B*A*GG */)
{
    int t = blockIdx.x * blockDim.x + threadIdx.x;
    if (t >= total) return;

    // decode input_dim (defensive: dataset scalar may be int32 or float32 bits)
    int raw = *dim_raw;
    float dimv = (raw > 0 && raw < (1 << 20)) ? (float)raw : __int_as_float(raw);
    float stride_f = dimv / (float)G;            // 8.0 for this head

    // t = (b*A + a)*GG + hw  -> consecutive threads share (b,a), consecutive hw
    int hw = t % GG;
    int ba = t / GG;
    int a  = ba % N_ANCH;
    int b  = ba / N_ANCH;

    float gx = (float)(hw % G);
    float gy = (float)(hw / G);

    // anchors in input-image pixels (anc/stride later *stride cancels)
    const float anch_w[N_ANCH] = {12.f, 19.f, 40.f};
    const float anch_h[N_ANCH] = {16.f, 36.f, 28.f};
    float aw = anch_w[a], ah = anch_h[a];

    // input:  element (b, a, c, hw) at ((b*A+a)*attrs + c)*GG + hw
    const float* __restrict__ in = x + (size_t)ba * N_ATTRS * GG + hw;
    // output: element (b, hw, a, c) at ((b*GG+hw)*A + a)*attrs + c
    float* __restrict__ o = out + ((size_t)((size_t)b * GG + hw) * N_ANCH + a) * N_ATTRS;

    // --- box attrs ---
    float v0 = in[0];
    float v1 = in[(size_t)GG];
    float v2 = in[(size_t)2 * GG];
    float v3 = in[(size_t)3 * GG];

    // sigmoid via fast exp: 1/(1+e^-v)
    float s0 = 1.0f / (1.0f + __expf(-v0));
    float s1 = 1.0f / (1.0f + __expf(-v1));

    const float half_off = (SCALE_XY - 1.0f) * 0.5f;
    o[0] = (fmaf(s0, SCALE_XY, gx - half_off)) * stride_f;
    o[1] = (fmaf(s1, SCALE_XY, gy - half_off)) * stride_f;
    o[2] = __expf(v2) * aw;
    o[3] = __expf(v3) * ah;

    // --- obj + 80 classes: sigmoid ---
    #pragma unroll 9
    for (int c = 4; c < N_ATTRS; ++c) {
        float v = in[(size_t)c * GG];
        o[c] = 1.0f / (1.0f + __expf(-v));
    }
}

extern "C" void kernel_launch(void* const* d_in, const int* in_sizes, int n_in,
                              void* d_out, int out_size)
{
    const float* x       = (const float*)d_in[0];
    const int*   dim_raw = (const int*)d_in[1];
    float*       out     = (float*)d_out;

    // n = B * A*attrs * G*G ; A*attrs = 255, B = 16 for this problem
    int n  = in_sizes[0];
    int B  = 16;
    int GG = n / (N_ANCH * N_ATTRS * B);     // 5776
    int G  = (int)(sqrtf((float)GG) + 0.5f); // 76

    int total = B * N_ANCH * GG;             // 277,248 threads
    int threads = 256;
    int blocks = (total + threads - 1) / threads;
    yolo_kernel<<<blocks, threads>>>(x, dim_raw, out, G, GG, total);
}

// round 2
// speedup vs baseline: 1.5201x; 1.5201x over previous
#include <cuda_runtime.h>
#include <math.h>

// YOLOv4 stride-8 head: [B, A*attrs, G, G] -> [B, G*G*A, attrs]
// B=16, A=3, attrs=85, G=76 for this problem.
//
// Round-2 design: thread <-> OUTPUT row. Compute 85 transformed attrs into a
// shared tile, then block-coalesced float4 copy to gmem (kills the 8x write
// sector amplification seen in round 1).

#define N_ANCH  3
#define N_ATTRS 85
#define SCALE_XY 1.2f
#define ROWS 128          // output rows per block == blockDim.x

__global__ __launch_bounds__(ROWS)
void yolo_kernel(const float* __restrict__ x,
                 const int*   __restrict__ dim_raw,
                 float*       __restrict__ out,
                 int G, int GG, int total_rows /* B*GG*A */)
{
    __shared__ float tile[ROWS * N_ATTRS];   // 43520 B, bank-conflict-free

    const int tid   = threadIdx.x;
    const int rbase = blockIdx.x * ROWS;
    const int r     = rbase + tid;           // global output row (b, hw, a)

    if (r < total_rows) {
        // decode input_dim (int32 or float32 bits)
        int raw = *dim_raw;
        float dimv = (raw > 0 && raw < (1 << 20)) ? (float)raw : __int_as_float(raw);
        float stride_f = dimv / (float)G;     // 8.0

        const int ga  = GG * N_ANCH;          // rows per batch image
        int b   = r / ga;
        int rem = r - b * ga;
        int hw  = rem / N_ANCH;
        int a   = rem - hw * N_ANCH;

        float gx = (float)(hw % G);
        float gy = (float)(hw / G);

        const float anch_w[N_ANCH] = {12.f, 19.f, 40.f};
        const float anch_h[N_ANCH] = {16.f, 36.f, 28.f};
        float aw = anch_w[a], ah = anch_h[a];

        // input element (b, a, c, hw): ((b*A + a)*attrs + c)*GG + hw
        const float* __restrict__ in = x + ((size_t)(b * N_ANCH + a) * N_ATTRS) * GG + hw;
        float* __restrict__ row = tile + tid * N_ATTRS;

        float v0 = in[0];
        float v1 = in[(size_t)GG];
        float v2 = in[(size_t)2 * GG];
        float v3 = in[(size_t)3 * GG];

        float s0 = 1.0f / (1.0f + __expf(-v0));
        float s1 = 1.0f / (1.0f + __expf(-v1));

        const float half_off = (SCALE_XY - 1.0f) * 0.5f;
        row[0] = fmaf(s0, SCALE_XY, gx - half_off) * stride_f;
        row[1] = fmaf(s1, SCALE_XY, gy - half_off) * stride_f;
        row[2] = __expf(v2) * aw;
        row[3] = __expf(v3) * ah;

        #pragma unroll 9
        for (int c = 4; c < N_ATTRS; ++c) {
            float v = in[(size_t)c * GG];
            row[c] = 1.0f / (1.0f + __expf(-v));
        }
    }
    __syncthreads();

    // Coalesced copy: tile -> out[rbase*85 .. ]
    int rows_here = total_rows - rbase;
    if (rows_here > ROWS) rows_here = ROWS;
    int nf  = rows_here * N_ATTRS;            // floats to copy
    int nf4 = nf >> 2;                        // float4 count (block base is 16B-aligned)

    const float4* __restrict__ s4 = (const float4*)tile;
    float4* __restrict__ o4 = (float4*)(out + (size_t)rbase * N_ATTRS);

    for (int i = tid; i < nf4; i += ROWS)
        o4[i] = s4[i];

    // scalar tail (only possible in the last partial block)
    for (int i = (nf4 << 2) + tid; i < nf; i += ROWS)
        out[(size_t)rbase * N_ATTRS + i] = tile[i];
}

extern "C" void kernel_launch(void* const* d_in, const int* in_sizes, int n_in,
                              void* d_out, int out_size)
{
    const float* x       = (const float*)d_in[0];
    const int*   dim_raw = (const int*)d_in[1];
    float*       out     = (float*)d_out;

    int n  = in_sizes[0];                       // B * 255 * G*G
    int B  = 16;
    int GG = n / (N_ANCH * N_ATTRS * B);        // 5776
    int G  = (int)(sqrtf((float)GG) + 0.5f);    // 76

    int total_rows = B * GG * N_ANCH;           // 277,248
    int blocks = (total_rows + ROWS - 1) / ROWS;
    yolo_kernel<<<blocks, ROWS>>>(x, dim_raw, out, G, GG, total_rows);
}

// round 3
// speedup vs baseline: 2.7352x; 1.7994x over previous
#include <cuda_runtime.h>
#include <math.h>

// YOLOv4 stride-8 head: [B, A*attrs, G, G] -> [B, G*G*A, attrs]
// B=16, A=3, attrs=85, G=76.
//
// Round-3: block = (batch, 32-wide hw tile) x all 3 anchors.
//   load  : warp-per-row coalesced 128B reads, transform in-register
//   smem  : transpose write, lane stride 255 (31 mod 32) -> conflict-free
//   store : tile is contiguous in output -> pure float4 streaming

#define N_ANCH   3
#define N_ATTRS  85
#define N_ROWS   255            // A * attrs
#define SCALE_XY 1.2f
#define HW_TILE  32
#define NTHREADS 256

__global__ __launch_bounds__(NTHREADS)
void yolo_kernel(const float* __restrict__ x,
                 const int*   __restrict__ dim_raw,
                 float*       __restrict__ out,
                 int G, int GG, int n_tiles)
{
    __shared__ float tile[HW_TILE * N_ROWS];   // 32640 B

    const int tid = threadIdx.x;
    const int b   = blockIdx.x / n_tiles;
    const int t   = blockIdx.x - b * n_tiles;
    const int hw0 = t * HW_TILE;
    int cnt = GG - hw0; if (cnt > HW_TILE) cnt = HW_TILE;

    // decode input_dim (int32 or float32 bits)
    int raw = *dim_raw;
    float dimv = (raw > 0 && raw < (1 << 20)) ? (float)raw : __int_as_float(raw);
    const float stride_f = dimv / (float)G;          // 8.0
    const float half_off = (SCALE_XY - 1.0f) * 0.5f;

    // input rows for this batch: row = a*85 + c, element at row*GG + hw
    const float* __restrict__ inb = x + (size_t)b * N_ROWS * GG + hw0;

    #pragma unroll 8
    for (int i = tid; i < N_ROWS * HW_TILE; i += NTHREADS) {
        int row = i >> 5;                 // a*85 + c   (whole warp shares row)
        int col = i & 31;
        if (col < cnt) {
            float v = inb[(size_t)row * GG + col];
            int a = row / N_ATTRS;
            int c = row - a * N_ATTRS;

            float r;
            if (c >= 4) {
                r = 1.0f / (1.0f + __expf(-v));
            } else if (c < 2) {
                int hw = hw0 + col;
                float g = (c == 0) ? (float)(hw % G) : (float)(hw / G);
                float s = 1.0f / (1.0f + __expf(-v));
                r = fmaf(s, SCALE_XY, g - half_off) * stride_f;
            } else {
                // anchors in input-image pixels (grid-anchor * stride cancels)
                float aw = (a == 0) ? 12.f : (a == 1) ? 19.f : 40.f;
                float ah = (a == 0) ? 16.f : (a == 1) ? 36.f : 28.f;
                r = __expf(v) * ((c == 2) ? aw : ah);
            }
            // transpose: (hw, a, c) ; lane stride 255 -> conflict-free
            tile[(col * N_ANCH + a) * N_ATTRS + c] = r;
        }
    }
    __syncthreads();

    // contiguous streaming store: cnt*255 floats (always divisible by 4 here,
    // scalar tail kept for generality)
    const int nf  = cnt * N_ROWS;
    const int nf4 = nf >> 2;
    const float4* __restrict__ s4 = (const float4*)tile;
    float*  __restrict__ obase = out + ((size_t)b * GG + hw0) * N_ROWS;
    float4* __restrict__ o4 = (float4*)obase;

    #pragma unroll 4
    for (int i = tid; i < nf4; i += NTHREADS)
        o4[i] = s4[i];
    for (int i = (nf4 << 2) + tid; i < nf; i += NTHREADS)
        obase[i] = tile[i];
}

extern "C" void kernel_launch(void* const* d_in, const int* in_sizes, int n_in,
                              void* d_out, int out_size)
{
    const float* x       = (const float*)d_in[0];
    const int*   dim_raw = (const int*)d_in[1];
    float*       out     = (float*)d_out;

    int n  = in_sizes[0];                        // B * 255 * G*G
    int B  = 16;
    int GG = n / (N_ROWS * B);                   // 5776
    int G  = (int)(sqrtf((float)GG) + 0.5f);     // 76

    int n_tiles = (GG + HW_TILE - 1) / HW_TILE;  // 181
    int blocks  = B * n_tiles;                   // 2896
    yolo_kernel<<<blocks, NTHREADS>>>(x, dim_raw, out, G, GG, n_tiles);
}

// round 4
// speedup vs baseline: 4.2297x; 1.5464x over previous
#include <cuda_runtime.h>
#include <math.h>

// YOLOv4 stride-8 head: [B, A*attrs, G, G] -> [B, G*G*A, attrs]
// B=16, A=3, attrs=85, G=76.
//
// Round-4: same tiling as round 3 (block = batch x 32-hw tile x 3 anchors)
// but the load/transform phase is float4-vectorized: 1 LDG.128 per 4 elems,
// one branch per float4 (all 4 share attr index c), /85 replaced by compares.
// Smem transpose scatter is conflict-free (verified bank math). Store phase
// remains contiguous float4 streaming.

#define N_ANCH   3
#define N_ATTRS  85
#define N_ROWS   255            // A * attrs
#define SCALE_XY 1.2f
#define HW_TILE  32
#define Q_PER_ROW (HW_TILE / 4) // 8 float4 per row
#define NTHREADS 256

__global__ __launch_bounds__(NTHREADS)
void yolo_kernel(const float* __restrict__ x,
                 const int*   __restrict__ dim_raw,
                 float*       __restrict__ out,
                 int G, int GG, int n_tiles)
{
    __shared__ float tile[HW_TILE * N_ROWS];   // 32640 B

    const int tid = threadIdx.x;
    const int b   = blockIdx.x / n_tiles;
    const int t   = blockIdx.x - b * n_tiles;
    const int hw0 = t * HW_TILE;
    int cnt = GG - hw0; if (cnt > HW_TILE) cnt = HW_TILE;   // 32 or 16 here

    // decode input_dim (int32 or float32 bits)
    int raw = *dim_raw;
    float dimv = (raw > 0 && raw < (1 << 20)) ? (float)raw : __int_as_float(raw);
    const float stride_f = dimv / (float)G;          // 8.0
    const float half_off = (SCALE_XY - 1.0f) * 0.5f;

    const float* __restrict__ inb = x + (size_t)b * N_ROWS * GG + hw0;

    // ---- load + transform: one float4 (4 consecutive hw of one row) per iter
    #pragma unroll 4
    for (int i = tid; i < N_ROWS * Q_PER_ROW; i += NTHREADS) {
        int row = i >> 3;            // a*85 + c
        int q   = i & 7;
        int col0 = q << 2;
        if (col0 < cnt) {            // cnt is a multiple of 4 for this shape
            float4 v = *(const float4*)(inb + (size_t)row * GG + col0);

            int a = (row >= 2 * N_ATTRS) ? 2 : (row >= N_ATTRS) ? 1 : 0;
            int c = row - a * N_ATTRS;

            float4 r;
            if (c >= 4) {
                r.x = 1.0f / (1.0f + __expf(-v.x));
                r.y = 1.0f / (1.0f + __expf(-v.y));
                r.z = 1.0f / (1.0f + __expf(-v.z));
                r.w = 1.0f / (1.0f + __expf(-v.w));
            } else if (c < 2) {
                int hw = hw0 + col0;
                float g0, g1, g2, g3;
                if (c == 0) {
                    g0 = (float)((hw + 0) % G); g1 = (float)((hw + 1) % G);
                    g2 = (float)((hw + 2) % G); g3 = (float)((hw + 3) % G);
                } else {
                    g0 = (float)((hw + 0) / G); g1 = (float)((hw + 1) / G);
                    g2 = (float)((hw + 2) / G); g3 = (float)((hw + 3) / G);
                }
                float s0 = 1.0f / (1.0f + __expf(-v.x));
                float s1 = 1.0f / (1.0f + __expf(-v.y));
                float s2 = 1.0f / (1.0f + __expf(-v.z));
                float s3 = 1.0f / (1.0f + __expf(-v.w));
                r.x = fmaf(s0, SCALE_XY, g0 - half_off) * stride_f;
                r.y = fmaf(s1, SCALE_XY, g1 - half_off) * stride_f;
                r.z = fmaf(s2, SCALE_XY, g2 - half_off) * stride_f;
                r.w = fmaf(s3, SCALE_XY, g3 - half_off) * stride_f;
            } else {
                // anchors in input-image pixels (grid-anchor * stride cancels)
                float aw = (a == 0) ? 12.f : (a == 1) ? 19.f : 40.f;
                float ah = (a == 0) ? 16.f : (a == 1) ? 36.f : 28.f;
                float m = (c == 2) ? aw : ah;
                r.x = __expf(v.x) * m;
                r.y = __expf(v.y) * m;
                r.z = __expf(v.z) * m;
                r.w = __expf(v.w) * m;
            }

            // transpose scatter: tile[(col*3 + a)*85 + c], conflict-free
            float* __restrict__ dst = tile + (size_t)(col0 * N_ANCH + a) * N_ATTRS + c;
            dst[0]           = r.x;
            dst[N_ROWS]      = r.y;
            dst[2 * N_ROWS]  = r.z;
            dst[3 * N_ROWS]  = r.w;
        }
    }
    __syncthreads();

    // ---- contiguous streaming store: cnt*255 floats
    const int nf  = cnt * N_ROWS;
    const int nf4 = nf >> 2;
    const float4* __restrict__ s4 = (const float4*)tile;
    float*  __restrict__ obase = out + ((size_t)b * GG + hw0) * N_ROWS;
    float4* __restrict__ o4 = (float4*)obase;

    #pragma unroll 4
    for (int i = tid; i < nf4; i += NTHREADS)
        o4[i] = s4[i];
    for (int i = (nf4 << 2) + tid; i < nf; i += NTHREADS)
        obase[i] = tile[i];
}

extern "C" void kernel_launch(void* const* d_in, const int* in_sizes, int n_in,
                              void* d_out, int out_size)
{
    const float* x       = (const float*)d_in[0];
    const int*   dim_raw = (const int*)d_in[1];
    float*       out     = (float*)d_out;

    int n  = in_sizes[0];                        // B * 255 * G*G
    int B  = 16;
    int GG = n / (N_ROWS * B);                   // 5776
    int G  = (int)(sqrtf((float)GG) + 0.5f);     // 76

    int n_tiles = (GG + HW_TILE - 1) / HW_TILE;  // 181
    int blocks  = B * n_tiles;                   // 2896
    yolo_kernel<<<blocks, NTHREADS>>>(x, dim_raw, out, G, GG, n_tiles);
}

// round 5
// speedup vs baseline: 4.9250x; 1.1644x over previous
#include <cuda_runtime.h>
#include <math.h>
#include <stdint.h>

// YOLOv4 stride-8 head: [B, A*attrs, G, G] -> [B, G*G*A, attrs]
// B=16, A=3, attrs=85, G=76.
//
// Round-5: round-4 tiling (block = batch x 32-hw x 3 anchors) with:
//  - fully-unrolled float4 load/transform (front-batched LDG.128, MLP=8)
//  - conflict-free smem transpose scatter
//  - single 1D bulk TMA store (cp.async.bulk) instead of LDS/STG copy loop

#define N_ANCH   3
#define N_ATTRS  85
#define N_ROWS   255            // A * attrs
#define SCALE_XY 1.2f
#define HW_TILE  32
#define Q_PER_ROW (HW_TILE / 4) // 8 float4 per row
#define NTHREADS 256
#define TILE_ELEMS (HW_TILE * N_ROWS)      // 8160 floats
#define ITERS_PER_THREAD (N_ROWS * Q_PER_ROW / NTHREADS)  // 2040/256 -> 7 full + rem

__device__ __forceinline__ uint32_t smem_u32(const void* p) {
    uint32_t a;
    asm("{ .reg .u64 t; cvta.to.shared.u64 t, %1; cvt.u32.u64 %0, t; }"
        : "=r"(a) : "l"(p));
    return a;
}

__device__ __forceinline__ void transform4(float4 v, int row, int col0, int hw0,
                                           int G, float stride_f, float half_off,
                                           float* __restrict__ tile)
{
    int a = (row >= 2 * N_ATTRS) ? 2 : (row >= N_ATTRS) ? 1 : 0;
    int c = row - a * N_ATTRS;

    float4 r;
    if (c >= 4) {
        r.x = 1.0f / (1.0f + __expf(-v.x));
        r.y = 1.0f / (1.0f + __expf(-v.y));
        r.z = 1.0f / (1.0f + __expf(-v.z));
        r.w = 1.0f / (1.0f + __expf(-v.w));
    } else if (c < 2) {
        int hw = hw0 + col0;
        float g0, g1, g2, g3;
        if (c == 0) {
            g0 = (float)((hw + 0) % G); g1 = (float)((hw + 1) % G);
            g2 = (float)((hw + 2) % G); g3 = (float)((hw + 3) % G);
        } else {
            g0 = (float)((hw + 0) / G); g1 = (float)((hw + 1) / G);
            g2 = (float)((hw + 2) / G); g3 = (float)((hw + 3) / G);
        }
        float s0 = 1.0f / (1.0f + __expf(-v.x));
        float s1 = 1.0f / (1.0f + __expf(-v.y));
        float s2 = 1.0f / (1.0f + __expf(-v.z));
        float s3 = 1.0f / (1.0f + __expf(-v.w));
        r.x = fmaf(s0, SCALE_XY, g0 - half_off) * stride_f;
        r.y = fmaf(s1, SCALE_XY, g1 - half_off) * stride_f;
        r.z = fmaf(s2, SCALE_XY, g2 - half_off) * stride_f;
        r.w = fmaf(s3, SCALE_XY, g3 - half_off) * stride_f;
    } else {
        float aw = (a == 0) ? 12.f : (a == 1) ? 19.f : 40.f;
        float ah = (a == 0) ? 16.f : (a == 1) ? 36.f : 28.f;
        float m = (c == 2) ? aw : ah;
        r.x = __expf(v.x) * m;
        r.y = __expf(v.y) * m;
        r.z = __expf(v.z) * m;
        r.w = __expf(v.w) * m;
    }

    float* __restrict__ dst = tile + (size_t)(col0 * N_ANCH + a) * N_ATTRS + c;
    dst[0]          = r.x;
    dst[N_ROWS]     = r.y;
    dst[2 * N_ROWS] = r.z;
    dst[3 * N_ROWS] = r.w;
}

__global__ __launch_bounds__(NTHREADS)
void yolo_kernel(const float* __restrict__ x,
                 const int*   __restrict__ dim_raw,
                 float*       __restrict__ out,
                 int G, int GG, int n_tiles)
{
    __shared__ __align__(16) float tile[TILE_ELEMS];   // 32640 B

    const int tid = threadIdx.x;
    const int b   = blockIdx.x / n_tiles;
    const int t   = blockIdx.x - b * n_tiles;
    const int hw0 = t * HW_TILE;
    int cnt = GG - hw0; if (cnt > HW_TILE) cnt = HW_TILE;   // 32 or 16

    int raw = *dim_raw;
    float dimv = (raw > 0 && raw < (1 << 20)) ? (float)raw : __int_as_float(raw);
    const float stride_f = dimv / (float)G;          // 8.0
    const float half_off = (SCALE_XY - 1.0f) * 0.5f;

    const float* __restrict__ inb = x + (size_t)b * N_ROWS * GG + hw0;
    const int total_q = N_ROWS * Q_PER_ROW;          // 2040

    if (cnt == HW_TILE) {
        // fast path: full tile, fully unrolled -> 8 front-batched LDG.128
        #pragma unroll
        for (int k = 0; k < 8; ++k) {
            int i = tid + k * NTHREADS;
            if (i < total_q) {
                int row  = i >> 3;
                int col0 = (i & 7) << 2;
                float4 v = *(const float4*)(inb + (size_t)row * GG + col0);
                transform4(v, row, col0, hw0, G, stride_f, half_off, tile);
            }
        }
    } else {
        #pragma unroll 4
        for (int i = tid; i < total_q; i += NTHREADS) {
            int row  = i >> 3;
            int col0 = (i & 7) << 2;
            if (col0 < cnt) {
                float4 v = *(const float4*)(inb + (size_t)row * GG + col0);
                transform4(v, row, col0, hw0, G, stride_f, half_off, tile);
            }
        }
    }
    __syncthreads();

    // ---- single 1D bulk TMA store: tile -> out (contiguous, 16B aligned) ----
    if (tid == 0) {
        asm volatile("fence.proxy.async.shared::cta;" ::: "memory");
        float* gdst = out + ((size_t)b * GG + hw0) * N_ROWS;
        uint32_t sa = smem_u32(tile);
        uint32_t bytes = (uint32_t)(cnt * N_ROWS * sizeof(float));  // mult of 16
        asm volatile(
            "cp.async.bulk.global.shared::cta.bulk_group [%0], [%1], %2;"
            :: "l"(gdst), "r"(sa), "r"(bytes) : "memory");
        asm volatile("cp.async.bulk.commit_group;" ::: "memory");
        asm volatile("cp.async.bulk.wait_group 0;" ::: "memory");
    }
}

extern "C" void kernel_launch(void* const* d_in, const int* in_sizes, int n_in,
                              void* d_out, int out_size)
{
    const float* x       = (const float*)d_in[0];
    const int*   dim_raw = (const int*)d_in[1];
    float*       out     = (float*)d_out;

    int n  = in_sizes[0];                        // B * 255 * G*G
    int B  = 16;
    int GG = n / (N_ROWS * B);                   // 5776
    int G  = (int)(sqrtf((float)GG) + 0.5f);     // 76

    int n_tiles = (GG + HW_TILE - 1) / HW_TILE;  // 181
    int blocks  = B * n_tiles;                   // 2896
    yolo_kernel<<<blocks, NTHREADS>>>(x, dim_raw, out, G, GG, n_tiles);
}

// round 6
// speedup vs baseline: 5.3533x; 1.0870x over previous
#include <cuda_runtime.h>
#include <math.h>
#include <stdint.h>

// YOLOv4 stride-8 head: [B, A*attrs, G, G] -> [B, G*G*A, attrs]
// B=16, A=3, attrs=85, G=76.
//
// Round-6: round-5 structure (fully-unrolled LDG.128 load/transform,
// conflict-free smem transpose, single bulk TMA store) with the sigmoid
// reciprocal switched to __fdividef (div.approx) to kill the full-IEEE
// division sequence.

#define N_ANCH   3
#define N_ATTRS  85
#define N_ROWS   255            // A * attrs
#define SCALE_XY 1.2f
#define HW_TILE  32
#define Q_PER_ROW (HW_TILE / 4) // 8 float4 per row
#define NTHREADS 256
#define TILE_ELEMS (HW_TILE * N_ROWS)      // 8160 floats

__device__ __forceinline__ uint32_t smem_u32(const void* p) {
    uint32_t a;
    asm("{ .reg .u64 t; cvta.to.shared.u64 t, %1; cvt.u32.u64 %0, t; }"
        : "=r"(a) : "l"(p));
    return a;
}

__device__ __forceinline__ float fast_sigmoid(float v) {
    // rcp.approx path: mul + ex2 + fadd + rcp  (rel err ~2^-21)
    return __fdividef(1.0f, 1.0f + __expf(-v));
}

__device__ __forceinline__ void transform4(float4 v, int row, int col0, int hw0,
                                           int G, float stride_f, float half_off,
                                           float* __restrict__ tile)
{
    int a = (row >= 2 * N_ATTRS) ? 2 : (row >= N_ATTRS) ? 1 : 0;
    int c = row - a * N_ATTRS;

    float4 r;
    if (c >= 4) {
        r.x = fast_sigmoid(v.x);
        r.y = fast_sigmoid(v.y);
        r.z = fast_sigmoid(v.z);
        r.w = fast_sigmoid(v.w);
    } else if (c < 2) {
        int hw = hw0 + col0;
        float g0, g1, g2, g3;
        if (c == 0) {
            g0 = (float)((hw + 0) % G); g1 = (float)((hw + 1) % G);
            g2 = (float)((hw + 2) % G); g3 = (float)((hw + 3) % G);
        } else {
            g0 = (float)((hw + 0) / G); g1 = (float)((hw + 1) / G);
            g2 = (float)((hw + 2) / G); g3 = (float)((hw + 3) / G);
        }
        float s0 = fast_sigmoid(v.x);
        float s1 = fast_sigmoid(v.y);
        float s2 = fast_sigmoid(v.z);
        float s3 = fast_sigmoid(v.w);
        r.x = fmaf(s0, SCALE_XY, g0 - half_off) * stride_f;
        r.y = fmaf(s1, SCALE_XY, g1 - half_off) * stride_f;
        r.z = fmaf(s2, SCALE_XY, g2 - half_off) * stride_f;
        r.w = fmaf(s3, SCALE_XY, g3 - half_off) * stride_f;
    } else {
        float aw = (a == 0) ? 12.f : (a == 1) ? 19.f : 40.f;
        float ah = (a == 0) ? 16.f : (a == 1) ? 36.f : 28.f;
        float m = (c == 2) ? aw : ah;
        r.x = __expf(v.x) * m;
        r.y = __expf(v.y) * m;
        r.z = __expf(v.z) * m;
        r.w = __expf(v.w) * m;
    }

    float* __restrict__ dst = tile + (size_t)(col0 * N_ANCH + a) * N_ATTRS + c;
    dst[0]          = r.x;
    dst[N_ROWS]     = r.y;
    dst[2 * N_ROWS] = r.z;
    dst[3 * N_ROWS] = r.w;
}

__global__ __launch_bounds__(NTHREADS)
void yolo_kernel(const float* __restrict__ x,
                 const int*   __restrict__ dim_raw,
                 float*       __restrict__ out,
                 int G, int GG, int n_tiles)
{
    __shared__ __align__(16) float tile[TILE_ELEMS];   // 32640 B

    const int tid = threadIdx.x;
    const int b   = blockIdx.x / n_tiles;
    const int t   = blockIdx.x - b * n_tiles;
    const int hw0 = t * HW_TILE;
    int cnt = GG - hw0; if (cnt > HW_TILE) cnt = HW_TILE;   // 32 or 16

    int raw = *dim_raw;
    float dimv = (raw > 0 && raw < (1 << 20)) ? (float)raw : __int_as_float(raw);
    const float stride_f = __fdividef(dimv, (float)G);      // 8.0
    const float half_off = (SCALE_XY - 1.0f) * 0.5f;

    const float* __restrict__ inb = x + (size_t)b * N_ROWS * GG + hw0;
    const int total_q = N_ROWS * Q_PER_ROW;          // 2040

    if (cnt == HW_TILE) {
        // fast path: full tile, fully unrolled -> 8 front-batched LDG.128
        #pragma unroll
        for (int k = 0; k < 8; ++k) {
            int i = tid + k * NTHREADS;
            if (i < total_q) {
                int row  = i >> 3;
                int col0 = (i & 7) << 2;
                float4 v = *(const float4*)(inb + (size_t)row * GG + col0);
                transform4(v, row, col0, hw0, G, stride_f, half_off, tile);
            }
        }
    } else {
        #pragma unroll 4
        for (int i = tid; i < total_q; i += NTHREADS) {
            int row  = i >> 3;
            int col0 = (i & 7) << 2;
            if (col0 < cnt) {
                float4 v = *(const float4*)(inb + (size_t)row * GG + col0);
                transform4(v, row, col0, hw0, G, stride_f, half_off, tile);
            }
        }
    }
    __syncthreads();

    // ---- single 1D bulk TMA store: tile -> out (contiguous, 16B aligned) ----
    if (tid == 0) {
        asm volatile("fence.proxy.async.shared::cta;" ::: "memory");
        float* gdst = out + ((size_t)b * GG + hw0) * N_ROWS;
        uint32_t sa = smem_u32(tile);
        uint32_t bytes = (uint32_t)(cnt * N_ROWS * sizeof(float));  // mult of 16
        asm volatile(
            "cp.async.bulk.global.shared::cta.bulk_group [%0], [%1], %2;"
            :: "l"(gdst), "r"(sa), "r"(bytes) : "memory");
        asm volatile("cp.async.bulk.commit_group;" ::: "memory");
        asm volatile("cp.async.bulk.wait_group 0;" ::: "memory");
    }
}

extern "C" void kernel_launch(void* const* d_in, const int* in_sizes, int n_in,
                              void* d_out, int out_size)
{
    const float* x       = (const float*)d_in[0];
    const int*   dim_raw = (const int*)d_in[1];
    float*       out     = (float*)d_out;

    int n  = in_sizes[0];                        // B * 255 * G*G
    int B  = 16;
    int GG = n / (N_ROWS * B);                   // 5776
    int G  = (int)(sqrtf((float)GG) + 0.5f);     // 76

    int n_tiles = (GG + HW_TILE - 1) / HW_TILE;  // 181
    int blocks  = B * n_tiles;                   // 2896
    yolo_kernel<<<blocks, NTHREADS>>>(x, dim_raw, out, G, GG, n_tiles);
}